// round 15
// baseline (speedup 1.0000x reference)
// R14: resubmit of R13 (never executed — broker infra failure). Planar global
// hi/lo + cp.async.cg 3-stage GEMM producer; consumer byte-identical to R10;
// attention = R10 form with planar hi/lo epilogue. Label: "gemm-cpasync-planar-retry".
#include <cuda_runtime.h>
#include <cuda_bf16.h>
#include <cstdint>

// Problem constants (Qwen2 GQA): B=2, S=2048, D=3584, H=28, KV=4, HD=128
#define Bn    2
#define Sn    2048
#define Dn    3584
#define Hn    28
#define KVn   4
#define HDn   128
#define NREP  7
#define Mn    (Bn * Sn)          // 4096
#define KVD   (KVn * HDn)        // 512
#define NQKV  (Dn + 2 * KVD)     // 4608
#define SCALE 0.08838834764831845f

// fp32 intermediates
__device__ float g_q[(size_t)Mn * Dn];
__device__ float g_k[(size_t)Mn * KVD];
__device__ float g_v[(size_t)Mn * KVD];
// planar bf16 hi/lo arrays (GEMM operands)
__device__ __nv_bfloat16 g_xhi[(size_t)Mn * Dn],   g_xlo[(size_t)Mn * Dn];    // x, later attn out
__device__ __nv_bfloat16 g_whi[(size_t)NQKV * Dn], g_wlo[(size_t)NQKV * Dn];  // wq|wk|wv
__device__ __nv_bfloat16 g_ohi[(size_t)Dn * Dn],   g_olo[(size_t)Dn * Dn];    // wo

// ===========================================================================
// helpers
// ===========================================================================
__device__ __forceinline__ void ldsm4(uint32_t& r0, uint32_t& r1,
                                      uint32_t& r2, uint32_t& r3, uint32_t addr)
{
    asm volatile("ldmatrix.sync.aligned.m8n8.x4.shared.b16 {%0,%1,%2,%3}, [%4];\n"
                 : "=r"(r0), "=r"(r1), "=r"(r2), "=r"(r3) : "r"(addr));
}

__device__ __forceinline__ void ldsm4t(uint32_t& r0, uint32_t& r1,
                                       uint32_t& r2, uint32_t& r3, uint32_t addr)
{
    asm volatile("ldmatrix.sync.aligned.m8n8.x4.trans.shared.b16 {%0,%1,%2,%3}, [%4];\n"
                 : "=r"(r0), "=r"(r1), "=r"(r2), "=r"(r3) : "r"(addr));
}

__device__ __forceinline__ void mma16816(float* c, const uint32_t* a,
                                         uint32_t b0, uint32_t b1)
{
    asm volatile(
        "mma.sync.aligned.m16n8k16.row.col.f32.bf16.bf16.f32 "
        "{%0,%1,%2,%3}, {%4,%5,%6,%7}, {%8,%9}, {%0,%1,%2,%3};\n"
        : "+f"(c[0]), "+f"(c[1]), "+f"(c[2]), "+f"(c[3])
        : "r"(a[0]), "r"(a[1]), "r"(a[2]), "r"(a[3]), "r"(b0), "r"(b1));
}

__device__ __forceinline__ void cpasync16(uint32_t dst, const void* src)
{
    asm volatile("cp.async.cg.shared.global [%0], [%1], 16;\n"
                 :: "r"(dst), "l"(src));
}

// ===========================================================================
// Fused pack: fp32 -> PLANAR hi/lo bf16 arrays (one launch, 16 elems/thread)
// ===========================================================================
#define PR0 ((size_t)Mn * Dn)
#define PR1 (PR0 + (size_t)Dn * Dn)
#define PR2 (PR1 + (size_t)KVD * Dn)
#define PR3 (PR2 + (size_t)KVD * Dn)
#define PR4 (PR3 + (size_t)Dn * Dn)
#define PACK_BLOCKS ((int)(PR4 / 16 / 256))

__global__ void pack_all_kernel(
    const float* __restrict__ x,  const float* __restrict__ wq,
    const float* __restrict__ wk, const float* __restrict__ wv,
    const float* __restrict__ wo)
{
    size_t base = ((size_t)blockIdx.x * blockDim.x + threadIdx.x) << 4;
    if (base >= PR4) return;

    const float* in;  __nv_bfloat16 *oh, *ol;  size_t off;
    if (base < PR0)      { in = x;  oh = g_xhi; ol = g_xlo;  off = base; }
    else if (base < PR1) { in = wq; oh = g_whi; ol = g_wlo;  off = base - PR0; }
    else if (base < PR2) { in = wk; oh = g_whi + (size_t)Dn * Dn;
                           ol = g_wlo + (size_t)Dn * Dn;     off = base - PR1; }
    else if (base < PR3) { in = wv; oh = g_whi + (size_t)(Dn + KVD) * Dn;
                           ol = g_wlo + (size_t)(Dn + KVD) * Dn; off = base - PR2; }
    else                 { in = wo; oh = g_ohi; ol = g_olo;  off = base - PR3; }

    float4 f[4];
#pragma unroll
    for (int j = 0; j < 4; ++j)
        f[j] = *(const float4*)(in + off + j * 4);

    __nv_bfloat16 hv[16], lv[16];
#pragma unroll
    for (int j = 0; j < 4; ++j) {
        float ff[4] = {f[j].x, f[j].y, f[j].z, f[j].w};
#pragma unroll
        for (int i = 0; i < 4; ++i) {
            __nv_bfloat16 hi = __float2bfloat16(ff[i]);
            hv[j * 4 + i] = hi;
            lv[j * 4 + i] = __float2bfloat16(ff[i] - __bfloat162float(hi));
        }
    }
    *(uint4*)(oh + off)     = *(const uint4*)(hv);
    *(uint4*)(oh + off + 8) = *(const uint4*)(hv + 8);
    *(uint4*)(ol + off)     = *(const uint4*)(lv);
    *(uint4*)(ol + off + 8) = *(const uint4*)(lv + 8);
}

// ===========================================================================
// Planar bf16-split3 GEMM, cp.async 3-stage producer.
// R10 consumer: 256 thr, 8 warps (4Mx2N), 32x64 warp tile, 2 CTAs/SM.
// smem per stage: Ahi|Alo|Whi|Wlo planes, 128 rows x 16 bf16, stride 24.
// ===========================================================================
#define LDP 24
#define PLANE (128 * LDP)              // 3072 bf16 = 6144 B
#define STAGE_E (4 * PLANE)
#define NSTAGE 3
#define GEMM_SMEM (NSTAGE * STAGE_E * 2)   // 73728 bytes

__global__ void __launch_bounds__(256, 2) gemm_planar_kernel(
    const __nv_bfloat16* __restrict__ Ahi, const __nv_bfloat16* __restrict__ Alo,
    const __nv_bfloat16* __restrict__ Whi, const __nv_bfloat16* __restrict__ Wlo,
    const float* __restrict__ bq, const float* __restrict__ bk,
    const float* __restrict__ bv,
    float* __restrict__ qd, float* __restrict__ kd, float* __restrict__ vd,
    int K, int rope_n,
    const float* __restrict__ cosT, const float* __restrict__ sinT)
{
    extern __shared__ __align__(16) __nv_bfloat16 smg[];

    const int tid  = threadIdx.x;
    const int lane = tid & 31, wid = tid >> 5;
    const int m0 = blockIdx.y << 7, n0 = blockIdx.x << 7;
    const int wm = (wid & 3) << 5;
    const int wn = (wid >> 2) << 6;

    // producer: row 0..127, col offset 0 or 8 (bf16 elems)
    const int pr = tid >> 1;
    const int pc = (tid & 1) << 3;
    const __nv_bfloat16* gAh = Ahi + (size_t)(m0 + pr) * K + pc;
    const __nv_bfloat16* gAl = Alo + (size_t)(m0 + pr) * K + pc;
    const __nv_bfloat16* gWh = Whi + (size_t)(n0 + pr) * K + pc;
    const __nv_bfloat16* gWl = Wlo + (size_t)(n0 + pr) * K + pc;
    const uint32_t soffB = (uint32_t)((pr * LDP + pc) * 2);   // byte offset in plane

    const int a_row  = wm + (lane & 15);
    const int a_coff = (lane >> 4) << 3;
    const int b_row  = wn + ((lane >> 4) << 3) + (lane & 7);
    const int b_coff = ((lane >> 3) & 1) << 3;
    const uint32_t s_base = (uint32_t)__cvta_generic_to_shared(smg);

    float acc[2][8][4];
#pragma unroll
    for (int i = 0; i < 2; ++i)
#pragma unroll
        for (int j = 0; j < 8; ++j)
#pragma unroll
            for (int e = 0; e < 4; ++e) acc[i][j][e] = 0.f;

    const int nit = K >> 4;

    // issue one stage's copies (4 x 16B per thread) + commit
#define ISSUE(s, kt) do {                                                   \
        uint32_t _d = s_base + (uint32_t)((s) * STAGE_E * 2) + soffB;       \
        cpasync16(_d,                 gAh + (kt));                          \
        cpasync16(_d + PLANE * 2,     gAl + (kt));                          \
        cpasync16(_d + 2 * PLANE * 2, gWh + (kt));                          \
        cpasync16(_d + 3 * PLANE * 2, gWl + (kt));                          \
        asm volatile("cp.async.commit_group;\n" ::: "memory");              \
    } while (0)

    ISSUE(0, 0);
    ISSUE(1, 16);

    for (int i = 0; i < nit; ++i) {
        if (i + 2 < nit) {
            asm volatile("cp.async.wait_group 1;\n" ::: "memory");
        } else {
            asm volatile("cp.async.wait_group 0;\n" ::: "memory");
        }
        __syncthreads();   // stage[i%3] ready; all warps done with stage[(i-1)%3]

        if (i + 2 < nit)
            ISSUE((i + 2) % NSTAGE, (i + 2) << 4);

        const uint32_t st  = s_base + (uint32_t)((i % NSTAGE) * STAGE_E * 2);
        const uint32_t ahi = st;
        const uint32_t alo = st + PLANE * 2;
        const uint32_t whi = st + 2 * PLANE * 2;
        const uint32_t wlo = st + 3 * PLANE * 2;

        uint32_t Ah[2][4], Al[2][4];
#pragma unroll
        for (int mi = 0; mi < 2; ++mi) {
            const uint32_t roff = (uint32_t)(((a_row + mi * 16) * LDP + a_coff) * 2);
            ldsm4(Ah[mi][0], Ah[mi][1], Ah[mi][2], Ah[mi][3], ahi + roff);
            ldsm4(Al[mi][0], Al[mi][1], Al[mi][2], Al[mi][3], alo + roff);
        }

#pragma unroll
        for (int nq = 0; nq < 4; ++nq) {
            const uint32_t broff = (uint32_t)(((nq * 16 + b_row) * LDP + b_coff) * 2);
            uint32_t Bh[4];
            ldsm4(Bh[0], Bh[1], Bh[2], Bh[3], whi + broff);
#pragma unroll
            for (int mi = 0; mi < 2; ++mi) {
                mma16816(acc[mi][nq * 2 + 0], Ah[mi], Bh[0], Bh[1]);   // hi*hi
                mma16816(acc[mi][nq * 2 + 1], Ah[mi], Bh[2], Bh[3]);
            }
#pragma unroll
            for (int mi = 0; mi < 2; ++mi) {
                mma16816(acc[mi][nq * 2 + 0], Al[mi], Bh[0], Bh[1]);   // lo*hi
                mma16816(acc[mi][nq * 2 + 1], Al[mi], Bh[2], Bh[3]);
            }
            uint32_t Bl[4];
            ldsm4(Bl[0], Bl[1], Bl[2], Bl[3], wlo + broff);
#pragma unroll
            for (int mi = 0; mi < 2; ++mi) {
                mma16816(acc[mi][nq * 2 + 0], Ah[mi], Bl[0], Bl[1]);   // hi*lo
                mma16816(acc[mi][nq * 2 + 1], Ah[mi], Bl[2], Bl[3]);
            }
        }
    }
#undef ISSUE

    // ---- epilogue: region dispatch + bias + optional RoPE (R10, fp32 out) ----
    const int g = lane >> 2, t = lane & 3;
#pragma unroll
    for (int mi = 0; mi < 2; ++mi) {
        const int row0 = m0 + wm + mi * 16 + g;
        const int row1 = row0 + 8;
        const int s0 = row0 & (Sn - 1);
        const int s1 = row1 & (Sn - 1);
#pragma unroll
        for (int ni = 0; ni < 8; ++ni) {
            const int col0 = n0 + wn + ni * 8 + t * 2;
            float* dst; int ccol, stride;
            float bb0 = 0.f, bb1 = 0.f;
            if (col0 < Dn) {
                dst = qd; ccol = col0; stride = Dn;
                if (bq) { bb0 = bq[col0]; bb1 = bq[col0 + 1]; }
            } else if (col0 < Dn + KVD) {
                dst = kd; ccol = col0 - Dn; stride = KVD;
                bb0 = bk[ccol]; bb1 = bk[ccol + 1];
            } else {
                dst = vd; ccol = col0 - Dn - KVD; stride = KVD;
                bb0 = bv[ccol]; bb1 = bv[ccol + 1];
            }
            float2 v0 = {acc[mi][ni][0] + bb0, acc[mi][ni][1] + bb1};
            float2 v1 = {acc[mi][ni][2] + bb0, acc[mi][ni][3] + bb1};
            if (col0 < rope_n) {
                const int p = (col0 & 127) >> 1;
                float c0 = cosT[s0 * 64 + p], sn0 = sinT[s0 * 64 + p];
                float c1 = cosT[s1 * 64 + p], sn1 = sinT[s1 * 64 + p];
                float2 r0 = {v0.x * c0 - v0.y * sn0, v0.x * sn0 + v0.y * c0};
                float2 r1 = {v1.x * c1 - v1.y * sn1, v1.x * sn1 + v1.y * c1};
                v0 = r0; v1 = r1;
            }
            *(float2*)(dst + (size_t)row0 * stride + ccol) = v0;
            *(float2*)(dst + (size_t)row1 * stride + ccol) = v1;
        }
    }
}

// ===========================================================================
// Tensor-core flash attention (R10 form: cvt4hl loaders from fp32 q/k/v;
// epilogue writes PLANAR hi/lo into g_xhi/g_xlo for the O projection).
// ===========================================================================
#define LQA 136
#define LPV 72
#define ATTN_SMEM ((2 * 128 * LQA + 4 * 64 * LQA + 2 * 128 * LPV) * 2)

__device__ __forceinline__ void cvt4hl(__nv_bfloat16* dhi, __nv_bfloat16* dlo, float4 v)
{
    float f[4] = {v.x, v.y, v.z, v.w};
    __nv_bfloat16 h[4], l[4];
#pragma unroll
    for (int i = 0; i < 4; ++i) {
        h[i] = __float2bfloat16(f[i]);
        l[i] = __float2bfloat16(f[i] - __bfloat162float(h[i]));
    }
    *(uint2*)dhi = *(const uint2*)h;
    *(uint2*)dlo = *(const uint2*)l;
}

__global__ void __launch_bounds__(256) attn_tc_kernel()
{
    extern __shared__ __align__(16) __nv_bfloat16 smb[];
    __nv_bfloat16* Qhi = smb;
    __nv_bfloat16* Qlo = Qhi + 128 * LQA;
    __nv_bfloat16* Khi = Qlo + 128 * LQA;
    __nv_bfloat16* Klo = Khi + 64 * LQA;
    __nv_bfloat16* Vhi = Klo + 64 * LQA;
    __nv_bfloat16* Vlo = Vhi + 64 * LQA;
    __nv_bfloat16* Phi = Vlo + 64 * LQA;
    __nv_bfloat16* Plo = Phi + 128 * LPV;

    const int qt = blockIdx.x, h = blockIdx.y, b = blockIdx.z;
    const int kvh = h / NREP;
    const int tid = threadIdx.x;
    const int lane = tid & 31, w = tid >> 5;
    const int qi0 = qt << 7;

    {
        const float* qg = g_q + (size_t)(b * Sn + qi0) * Dn + h * HDn;
        int r = tid >> 1, c0 = (tid & 1) << 6;
#pragma unroll
        for (int c = 0; c < 64; c += 4) {
            float4 v = *(const float4*)(qg + (size_t)r * Dn + c0 + c);
            cvt4hl(Qhi + r * LQA + c0 + c, Qlo + r * LQA + c0 + c, v);
        }
    }

    const int a_row_l = lane & 15;
    const int a_coff  = (lane >> 4) << 3;
    const int b_row_l = ((lane >> 4) << 3) + (lane & 7);
    const int b_coff  = ((lane >> 3) & 1) << 3;
    const int t_row = (((lane >> 3) & 1) << 3) + (lane & 7);
    const int t_col = (lane >> 4) << 3;

    const uint32_t qhi_b = (uint32_t)__cvta_generic_to_shared(Qhi);
    const uint32_t qlo_b = (uint32_t)__cvta_generic_to_shared(Qlo);
    const uint32_t khi_b = (uint32_t)__cvta_generic_to_shared(Khi);
    const uint32_t klo_b = (uint32_t)__cvta_generic_to_shared(Klo);
    const uint32_t vhi_b = (uint32_t)__cvta_generic_to_shared(Vhi);
    const uint32_t vlo_b = (uint32_t)__cvta_generic_to_shared(Vlo);
    const uint32_t phi_b = (uint32_t)__cvta_generic_to_shared(Phi);
    const uint32_t plo_b = (uint32_t)__cvta_generic_to_shared(Plo);

    const int g  = lane >> 2;
    const int t4 = lane & 3;
    const int qglob0 = qi0 + w * 16 + g;
    const int qglob1 = qglob0 + 8;

    float oacc[16][4];
#pragma unroll
    for (int i = 0; i < 16; ++i)
#pragma unroll
        for (int e = 0; e < 4; ++e) oacc[i][e] = 0.f;
    float m0 = -1e30f, m1 = -1e30f, l0 = 0.f, l1 = 0.f;

    const float* kg_base = g_k + (size_t)(b * Sn) * KVD + kvh * HDn;
    const float* vg_base = g_v + (size_t)(b * Sn) * KVD + kvh * HDn;

    const int jmax = qi0 + 64;
    for (int j0 = 0; j0 <= jmax; j0 += 64) {
        __syncthreads();
        {
            int r = tid >> 2, c0 = (tid & 3) << 5;
            const float* kg = kg_base + (size_t)(j0 + r) * KVD + c0;
            const float* vg = vg_base + (size_t)(j0 + r) * KVD + c0;
#pragma unroll
            for (int c = 0; c < 32; c += 4) {
                cvt4hl(Khi + r * LQA + c0 + c, Klo + r * LQA + c0 + c,
                       *(const float4*)(kg + c));
                cvt4hl(Vhi + r * LQA + c0 + c, Vlo + r * LQA + c0 + c,
                       *(const float4*)(vg + c));
            }
        }
        __syncthreads();

        float sacc[8][4];
#pragma unroll
        for (int i = 0; i < 8; ++i)
#pragma unroll
            for (int e = 0; e < 4; ++e) sacc[i][e] = 0.f;

#pragma unroll
        for (int pass = 0; pass < 3; ++pass) {
            const uint32_t ab = (pass == 2) ? qlo_b : qhi_b;
            const uint32_t bb = (pass == 1) ? klo_b : khi_b;
#pragma unroll
            for (int ks = 0; ks < 8; ++ks) {
                const int kk = ks << 4;
                uint32_t afr[4];
                ldsm4(afr[0], afr[1], afr[2], afr[3],
                      ab + (uint32_t)(((w * 16 + a_row_l) * LQA + kk + a_coff) * 2));
                uint32_t bfr[4][4];
#pragma unroll
                for (int nq = 0; nq < 4; ++nq)
                    ldsm4(bfr[nq][0], bfr[nq][1], bfr[nq][2], bfr[nq][3],
                          bb + (uint32_t)(((nq * 16 + b_row_l) * LQA + kk + b_coff) * 2));
#pragma unroll
                for (int nq = 0; nq < 4; ++nq) {
                    mma16816(sacc[nq * 2 + 0], afr, bfr[nq][0], bfr[nq][1]);
                    mma16816(sacc[nq * 2 + 1], afr, bfr[nq][2], bfr[nq][3]);
                }
            }
        }

#pragma unroll
        for (int nq = 0; nq < 8; ++nq) {
            int cb = j0 + nq * 8 + t4 * 2;
            float s0 = sacc[nq][0] * SCALE;
            float s1 = sacc[nq][1] * SCALE;
            float s2 = sacc[nq][2] * SCALE;
            float s3 = sacc[nq][3] * SCALE;
            if (cb     > qglob0) s0 = -1e30f;
            if (cb + 1 > qglob0) s1 = -1e30f;
            if (cb     > qglob1) s2 = -1e30f;
            if (cb + 1 > qglob1) s3 = -1e30f;
            sacc[nq][0] = s0; sacc[nq][1] = s1;
            sacc[nq][2] = s2; sacc[nq][3] = s3;
        }

        float rm0 = -1e30f, rm1 = -1e30f;
#pragma unroll
        for (int nq = 0; nq < 8; ++nq) {
            rm0 = fmaxf(rm0, fmaxf(sacc[nq][0], sacc[nq][1]));
            rm1 = fmaxf(rm1, fmaxf(sacc[nq][2], sacc[nq][3]));
        }
        rm0 = fmaxf(rm0, __shfl_xor_sync(0xffffffffu, rm0, 1));
        rm0 = fmaxf(rm0, __shfl_xor_sync(0xffffffffu, rm0, 2));
        rm1 = fmaxf(rm1, __shfl_xor_sync(0xffffffffu, rm1, 1));
        rm1 = fmaxf(rm1, __shfl_xor_sync(0xffffffffu, rm1, 2));
        float mn0 = fmaxf(m0, rm0), mn1 = fmaxf(m1, rm1);
        float al0 = __expf(m0 - mn0), al1 = __expf(m1 - mn1);

        __syncwarp();
        float rs0 = 0.f, rs1 = 0.f;
        const int prow0 = w * 16 + g;
#pragma unroll
        for (int nq = 0; nq < 8; ++nq) {
            int col = nq * 8 + t4 * 2;
            float p0 = __expf(sacc[nq][0] - mn0);
            float p1 = __expf(sacc[nq][1] - mn0);
            float p2 = __expf(sacc[nq][2] - mn1);
            float p3 = __expf(sacc[nq][3] - mn1);
            rs0 += p0 + p1;  rs1 += p2 + p3;
            __nv_bfloat162 h01, l01, h23, l23;
            h01.x = __float2bfloat16(p0);
            h01.y = __float2bfloat16(p1);
            l01.x = __float2bfloat16(p0 - __bfloat162float(h01.x));
            l01.y = __float2bfloat16(p1 - __bfloat162float(h01.y));
            h23.x = __float2bfloat16(p2);
            h23.y = __float2bfloat16(p3);
            l23.x = __float2bfloat16(p2 - __bfloat162float(h23.x));
            l23.y = __float2bfloat16(p3 - __bfloat162float(h23.y));
            *(__nv_bfloat162*)(Phi + prow0 * LPV + col)       = h01;
            *(__nv_bfloat162*)(Plo + prow0 * LPV + col)       = l01;
            *(__nv_bfloat162*)(Phi + (prow0 + 8) * LPV + col) = h23;
            *(__nv_bfloat162*)(Plo + (prow0 + 8) * LPV + col) = l23;
        }
        rs0 += __shfl_xor_sync(0xffffffffu, rs0, 1);
        rs0 += __shfl_xor_sync(0xffffffffu, rs0, 2);
        rs1 += __shfl_xor_sync(0xffffffffu, rs1, 1);
        rs1 += __shfl_xor_sync(0xffffffffu, rs1, 2);
        l0 = l0 * al0 + rs0;  l1 = l1 * al1 + rs1;
        m0 = mn0;  m1 = mn1;
#pragma unroll
        for (int nn = 0; nn < 16; ++nn) {
            oacc[nn][0] *= al0; oacc[nn][1] *= al0;
            oacc[nn][2] *= al1; oacc[nn][3] *= al1;
        }
        __syncwarp();

#pragma unroll
        for (int pass = 0; pass < 3; ++pass) {
            const uint32_t ab = (pass == 2) ? plo_b : phi_b;
            const uint32_t bb = (pass == 1) ? vlo_b : vhi_b;
#pragma unroll
            for (int ks = 0; ks < 4; ++ks) {
                const int kk = ks << 4;
                uint32_t afr[4];
                ldsm4(afr[0], afr[1], afr[2], afr[3],
                      ab + (uint32_t)(((w * 16 + a_row_l) * LPV + kk + a_coff) * 2));
#pragma unroll
                for (int nh = 0; nh < 8; ++nh) {
                    uint32_t b0, b1, b2, b3;
                    ldsm4t(b0, b1, b2, b3,
                           bb + (uint32_t)(((kk + t_row) * LQA + nh * 16 + t_col) * 2));
                    mma16816(oacc[nh * 2 + 0], afr, b0, b1);
                    mma16816(oacc[nh * 2 + 1], afr, b2, b3);
                }
            }
        }
    }

    // epilogue: normalize, write planar hi/lo into g_xhi / g_xlo
    float inv0 = 1.f / l0, inv1 = 1.f / l1;
    const size_t i0 = (size_t)(b * Sn + qglob0) * Dn + h * HDn;
    const size_t i1 = (size_t)(b * Sn + qglob1) * Dn + h * HDn;
#pragma unroll
    for (int nn = 0; nn < 16; ++nn) {
        int col = nn * 8 + t4 * 2;
        float v00 = oacc[nn][0] * inv0, v01 = oacc[nn][1] * inv0;
        float v10 = oacc[nn][2] * inv1, v11 = oacc[nn][3] * inv1;
        __nv_bfloat162 h0, l0p, h1, l1p;
        h0.x  = __float2bfloat16(v00);
        h0.y  = __float2bfloat16(v01);
        l0p.x = __float2bfloat16(v00 - __bfloat162float(h0.x));
        l0p.y = __float2bfloat16(v01 - __bfloat162float(h0.y));
        h1.x  = __float2bfloat16(v10);
        h1.y  = __float2bfloat16(v11);
        l1p.x = __float2bfloat16(v10 - __bfloat162float(h1.x));
        l1p.y = __float2bfloat16(v11 - __bfloat162float(h1.y));
        *(__nv_bfloat162*)(g_xhi + i0 + col) = h0;
        *(__nv_bfloat162*)(g_xlo + i0 + col) = l0p;
        *(__nv_bfloat162*)(g_xhi + i1 + col) = h1;
        *(__nv_bfloat162*)(g_xlo + i1 + col) = l1p;
    }
}

// ===========================================================================
// Launch
// ===========================================================================
extern "C" void kernel_launch(void* const* d_in, const int* in_sizes, int n_in,
                              void* d_out, int out_size)
{
    const float* x    = (const float*)d_in[0];
    const float* wq_w = (const float*)d_in[1];
    const float* wq_b = (const float*)d_in[2];
    const float* wk_w = (const float*)d_in[3];
    const float* wk_b = (const float*)d_in[4];
    const float* wv_w = (const float*)d_in[5];
    const float* wv_b = (const float*)d_in[6];
    const float* wo_w = (const float*)d_in[7];
    const float* fcos = (const float*)d_in[10];
    const float* fsin = (const float*)d_in[11];
    float* out = (float*)d_out;

    float *q_p, *k_p, *v_p;
    __nv_bfloat16 *xhi, *xlo, *whi, *wlo, *ohi, *olo;
    cudaGetSymbolAddress((void**)&q_p, g_q);
    cudaGetSymbolAddress((void**)&k_p, g_k);
    cudaGetSymbolAddress((void**)&v_p, g_v);
    cudaGetSymbolAddress((void**)&xhi, g_xhi);
    cudaGetSymbolAddress((void**)&xlo, g_xlo);
    cudaGetSymbolAddress((void**)&whi, g_whi);
    cudaGetSymbolAddress((void**)&wlo, g_wlo);
    cudaGetSymbolAddress((void**)&ohi, g_ohi);
    cudaGetSymbolAddress((void**)&olo, g_olo);

    // Fused pack: all 5 tensors -> planar hi/lo (one launch)
    pack_all_kernel<<<PACK_BLOCKS, 256>>>(x, wq_w, wk_w, wv_w, wo_w);

    cudaFuncSetAttribute(gemm_planar_kernel,
                         cudaFuncAttributeMaxDynamicSharedMemorySize, GEMM_SMEM);

    // Merged QKV projection + fused RoPE (fp32 outputs)
    gemm_planar_kernel<<<dim3(NQKV / 128, Mn / 128), 256, GEMM_SMEM>>>(
        xhi, xlo, whi, wlo, wq_b, wk_b, wv_b, q_p, k_p, v_p,
        Dn, Dn + KVD, fcos, fsin);

    // Flash attention (writes planar hi/lo into g_xhi/g_xlo)
    cudaFuncSetAttribute(attn_tc_kernel, cudaFuncAttributeMaxDynamicSharedMemorySize,
                         ATTN_SMEM);
    attn_tc_kernel<<<dim3(Sn / 128, Hn, Bn), 256, ATTN_SMEM>>>();

    // O projection straight into d_out (fp32, no rope, no bias)
    gemm_planar_kernel<<<dim3(Dn / 128, Mn / 128), 256, GEMM_SMEM>>>(
        xhi, xlo, ohi, olo, nullptr, nullptr, nullptr, out, out, out,
        Dn, 0, fcos, fsin);
}

// round 16
// speedup vs baseline: 1.0721x; 1.0721x over previous
// R15: revert to R10 config (best, 3456us) + single barrier per 32-K via
// half-iteration prefetch rotation (sync count halved, regs unchanged).
// Attention/pack = R10 exact. Label: "gemm-k32-halfpipe".
#include <cuda_runtime.h>
#include <cuda_bf16.h>
#include <cstdint>

// Problem constants (Qwen2 GQA): B=2, S=2048, D=3584, H=28, KV=4, HD=128
#define Bn    2
#define Sn    2048
#define Dn    3584
#define Hn    28
#define KVn   4
#define HDn   128
#define NREP  7
#define Mn    (Bn * Sn)          // 4096
#define KVD   (KVn * HDn)        // 512
#define NQKV  (Dn + 2 * KVD)     // 4608
#define SCALE 0.08838834764831845f

// fp32 intermediates
__device__ float g_q[(size_t)Mn * Dn];
__device__ float g_k[(size_t)Mn * KVD];
__device__ float g_v[(size_t)Mn * KVD];
// planar (hi,lo) bf16 pair arrays
__device__ __nv_bfloat162 g_ap   [(size_t)Mn   * Dn];   // x pairs, later attn pairs
__device__ __nv_bfloat162 g_wqkvp[(size_t)NQKV * Dn];   // wq|wk|wv stacked rows
__device__ __nv_bfloat162 g_wop  [(size_t)Dn   * Dn];

// ===========================================================================
// mma/ldsm helpers
// ===========================================================================
__device__ __forceinline__ void ldsm4(uint32_t& r0, uint32_t& r1,
                                      uint32_t& r2, uint32_t& r3, uint32_t addr)
{
    asm volatile("ldmatrix.sync.aligned.m8n8.x4.shared.b16 {%0,%1,%2,%3}, [%4];\n"
                 : "=r"(r0), "=r"(r1), "=r"(r2), "=r"(r3) : "r"(addr));
}

__device__ __forceinline__ void ldsm4t(uint32_t& r0, uint32_t& r1,
                                       uint32_t& r2, uint32_t& r3, uint32_t addr)
{
    asm volatile("ldmatrix.sync.aligned.m8n8.x4.trans.shared.b16 {%0,%1,%2,%3}, [%4];\n"
                 : "=r"(r0), "=r"(r1), "=r"(r2), "=r"(r3) : "r"(addr));
}

__device__ __forceinline__ void mma16816(float* c, const uint32_t* a,
                                         uint32_t b0, uint32_t b1)
{
    asm volatile(
        "mma.sync.aligned.m16n8k16.row.col.f32.bf16.bf16.f32 "
        "{%0,%1,%2,%3}, {%4,%5,%6,%7}, {%8,%9}, {%0,%1,%2,%3};\n"
        : "+f"(c[0]), "+f"(c[1]), "+f"(c[2]), "+f"(c[3])
        : "r"(a[0]), "r"(a[1]), "r"(a[2]), "r"(a[3]), "r"(b0), "r"(b1));
}

__device__ __forceinline__ __nv_bfloat162 hl_pair(float v)
{
    __nv_bfloat162 p;
    p.x = __float2bfloat16(v);
    p.y = __float2bfloat16(v - __bfloat162float(p.x));
    return p;
}

// ===========================================================================
// Fused pack (R9/R10, verified): fp32 -> interleaved (hi,lo) pair arrays
// ===========================================================================
#define PR0 ((size_t)Mn * Dn)
#define PR1 (PR0 + (size_t)Dn * Dn)
#define PR2 (PR1 + (size_t)KVD * Dn)
#define PR3 (PR2 + (size_t)KVD * Dn)
#define PR4 (PR3 + (size_t)Dn * Dn)
#define PACK_BLOCKS ((int)(PR4 / 16 / 256))

__global__ void pack_all_kernel(
    const float* __restrict__ x,  const float* __restrict__ wq,
    const float* __restrict__ wk, const float* __restrict__ wv,
    const float* __restrict__ wo)
{
    size_t base = ((size_t)blockIdx.x * blockDim.x + threadIdx.x) << 4;
    if (base >= PR4) return;

    const float* in;  __nv_bfloat162* out;  size_t off;
    if (base < PR0)      { in = x;  out = g_ap;                               off = base; }
    else if (base < PR1) { in = wq; out = g_wqkvp;                            off = base - PR0; }
    else if (base < PR2) { in = wk; out = g_wqkvp + (size_t)Dn * Dn;          off = base - PR1; }
    else if (base < PR3) { in = wv; out = g_wqkvp + (size_t)(Dn + KVD) * Dn;  off = base - PR2; }
    else                 { in = wo; out = g_wop;                              off = base - PR3; }

    float4 f[4];
#pragma unroll
    for (int j = 0; j < 4; ++j)
        f[j] = *(const float4*)(in + off + j * 4);

#pragma unroll
    for (int j = 0; j < 4; ++j) {
        float ff[4] = {f[j].x, f[j].y, f[j].z, f[j].w};
        __nv_bfloat162 o[4];
#pragma unroll
        for (int i = 0; i < 4; ++i)
            o[i] = hl_pair(ff[i]);
        *(uint4*)(out + off + j * 4) = *(const uint4*)o;
    }
}

// ===========================================================================
// Planar bf16-split3 GEMM, K-step 32, ONE barrier per step.
// R10 consumer (256 thr, 8 warps 4Mx2N, 32x64 warp tile, 2 CTAs/SM).
// smem stage: Ahi|Alo|Whi|Wlo planes, 128 rows x 32 bf16, row stride 40
// (80B = 5x16B: ldsm-aligned; 80r mod 128 -> 8 distinct 16B spans).
// Half-iteration prefetch rotation keeps register prefetch at 16 regs:
//   sub0: store half0 of next stage; load half1 of iter i+1; mma kk=0
//   sub1: store half1 of next stage; load half0 of iter i+2; mma kk=16
// ===========================================================================
#define LDP 40
#define PLANE (128 * LDP)              // 5120 bf16 = 10240 B
#define STAGE_E (4 * PLANE)            // 20480 bf16
#define GEMM_SMEM (2 * STAGE_E * 2)    // 81920 bytes

// split 8 (hi,lo) pairs (two uint4) into hi/lo planes (8+8 bf16)
__device__ __forceinline__ void split_store(__nv_bfloat16* hip, __nv_bfloat16* lop,
                                            uint4 p0, uint4 p1)
{
    uint2 h0, l0, h1, l1;
    h0.x = (p0.x & 0xFFFFu) | (p0.y << 16);
    h0.y = (p0.z & 0xFFFFu) | (p0.w << 16);
    l0.x = (p0.x >> 16)     | (p0.y & 0xFFFF0000u);
    l0.y = (p0.z >> 16)     | (p0.w & 0xFFFF0000u);
    h1.x = (p1.x & 0xFFFFu) | (p1.y << 16);
    h1.y = (p1.z & 0xFFFFu) | (p1.w << 16);
    l1.x = (p1.x >> 16)     | (p1.y & 0xFFFF0000u);
    l1.y = (p1.z >> 16)     | (p1.w & 0xFFFF0000u);
    *(uint2*)hip       = h0;  *(uint2*)(hip + 4) = h1;
    *(uint2*)lop       = l0;  *(uint2*)(lop + 4) = l1;
}

__global__ void __launch_bounds__(256, 2) gemm_pairs_kernel(
    const __nv_bfloat162* __restrict__ A, const __nv_bfloat162* __restrict__ W,
    const float* __restrict__ bq, const float* __restrict__ bk,
    const float* __restrict__ bv,
    float* __restrict__ qd, float* __restrict__ kd, float* __restrict__ vd,
    int K, int rope_n,
    const float* __restrict__ cosT, const float* __restrict__ sinT)
{
    extern __shared__ __align__(16) __nv_bfloat16 smg[];

    const int tid  = threadIdx.x;
    const int lane = tid & 31, wid = tid >> 5;
    const int m0 = blockIdx.y << 7, n0 = blockIdx.x << 7;
    const int wm = (wid & 3) << 5;
    const int wn = (wid >> 2) << 6;

    // producer: row 0..127, pair-col offset 0 or 8 within each 16-wide half
    const int pr = tid >> 1;
    const int pc = (tid & 1) << 3;
    const __nv_bfloat162* Ag = A + (size_t)(m0 + pr) * K + pc;
    const __nv_bfloat162* Wg = W + (size_t)(n0 + pr) * K + pc;
    const int soff = pr * LDP + pc;     // elem offset of half0 slot in a plane

    const int a_row  = wm + (lane & 15);
    const int a_coff = (lane >> 4) << 3;
    const int b_row  = wn + ((lane >> 4) << 3) + (lane & 7);
    const int b_coff = ((lane >> 3) & 1) << 3;
    const uint32_t s_base = (uint32_t)__cvta_generic_to_shared(smg);

    float acc[2][8][4];
#pragma unroll
    for (int i = 0; i < 2; ++i)
#pragma unroll
        for (int j = 0; j < 8; ++j)
#pragma unroll
            for (int e = 0; e < 4; ++e) acc[i][j][e] = 0.f;

#define LOADH(col) do {                                 \
        ra0 = *(const uint4*)(Ag + (col));              \
        ra1 = *(const uint4*)(Ag + (col) + 4);          \
        rw0 = *(const uint4*)(Wg + (col));              \
        rw1 = *(const uint4*)(Wg + (col) + 4);          \
    } while (0)
#define STOREH(basep, half) do {                                            \
        __nv_bfloat16* _s = (basep);                                        \
        split_store(_s + soff + (half) * 16,                                \
                    _s + PLANE + soff + (half) * 16, ra0, ra1);             \
        split_store(_s + 2 * PLANE + soff + (half) * 16,                    \
                    _s + 3 * PLANE + soff + (half) * 16, rw0, rw1);         \
    } while (0)

    uint4 ra0, ra1, rw0, rw1;
    // prologue: fill stage 0 (both halves) directly
    LOADH(0);   STOREH(smg, 0);
    LOADH(16);  STOREH(smg, 1);
    // prefetch half0 of iteration 1
    if (32 < K) LOADH(32);

    const int nit = K >> 5;
    for (int i = 0; i < nit; ++i) {
        __syncthreads();   // stage[cur] stores visible; prior reads of stage[nxt] done
        const int cur = i & 1;
        __nv_bfloat16* ns = smg + (cur ^ 1) * STAGE_E;
        const uint32_t st  = s_base + (uint32_t)(cur * STAGE_E * 2);
        const uint32_t ahi = st;
        const uint32_t alo = st + PLANE * 2;
        const uint32_t whi = st + 2 * PLANE * 2;
        const uint32_t wlo = st + 3 * PLANE * 2;

#pragma unroll
        for (int ks = 0; ks < 2; ++ks) {
            // producer rotation for this sub-step
            if (i + 1 < nit) {
                if (ks == 0) {
                    STOREH(ns, 0);
                    LOADH((i + 1) * 32 + 16);          // half1 of iter i+1
                } else {
                    STOREH(ns, 1);
                    if (i + 2 < nit) LOADH((i + 2) * 32);  // half0 of iter i+2
                }
            }

            const int kk = ks << 4;
            uint32_t Ah[2][4], Al[2][4];
#pragma unroll
            for (int mi = 0; mi < 2; ++mi) {
                const uint32_t roff = (uint32_t)(((a_row + mi * 16) * LDP + kk + a_coff) * 2);
                ldsm4(Ah[mi][0], Ah[mi][1], Ah[mi][2], Ah[mi][3], ahi + roff);
                ldsm4(Al[mi][0], Al[mi][1], Al[mi][2], Al[mi][3], alo + roff);
            }
#pragma unroll
            for (int nq = 0; nq < 4; ++nq) {
                const uint32_t broff = (uint32_t)(((nq * 16 + b_row) * LDP + kk + b_coff) * 2);
                uint32_t Bh[4];
                ldsm4(Bh[0], Bh[1], Bh[2], Bh[3], whi + broff);
#pragma unroll
                for (int mi = 0; mi < 2; ++mi) {
                    mma16816(acc[mi][nq * 2 + 0], Ah[mi], Bh[0], Bh[1]);   // hi*hi
                    mma16816(acc[mi][nq * 2 + 1], Ah[mi], Bh[2], Bh[3]);
                }
#pragma unroll
                for (int mi = 0; mi < 2; ++mi) {
                    mma16816(acc[mi][nq * 2 + 0], Al[mi], Bh[0], Bh[1]);   // lo*hi
                    mma16816(acc[mi][nq * 2 + 1], Al[mi], Bh[2], Bh[3]);
                }
                uint32_t Bl[4];
                ldsm4(Bl[0], Bl[1], Bl[2], Bl[3], wlo + broff);
#pragma unroll
                for (int mi = 0; mi < 2; ++mi) {
                    mma16816(acc[mi][nq * 2 + 0], Ah[mi], Bl[0], Bl[1]);   // hi*lo
                    mma16816(acc[mi][nq * 2 + 1], Ah[mi], Bl[2], Bl[3]);
                }
            }
        }
    }
#undef LOADH
#undef STOREH

    // ---- epilogue: region dispatch + bias + optional RoPE (R10) ----
    const int g = lane >> 2, t = lane & 3;
#pragma unroll
    for (int mi = 0; mi < 2; ++mi) {
        const int row0 = m0 + wm + mi * 16 + g;
        const int row1 = row0 + 8;
        const int s0 = row0 & (Sn - 1);
        const int s1 = row1 & (Sn - 1);
#pragma unroll
        for (int ni = 0; ni < 8; ++ni) {
            const int col0 = n0 + wn + ni * 8 + t * 2;
            float* dst; int ccol, stride;
            float bb0 = 0.f, bb1 = 0.f;
            if (col0 < Dn) {
                dst = qd; ccol = col0; stride = Dn;
                if (bq) { bb0 = bq[col0]; bb1 = bq[col0 + 1]; }
            } else if (col0 < Dn + KVD) {
                dst = kd; ccol = col0 - Dn; stride = KVD;
                bb0 = bk[ccol]; bb1 = bk[ccol + 1];
            } else {
                dst = vd; ccol = col0 - Dn - KVD; stride = KVD;
                bb0 = bv[ccol]; bb1 = bv[ccol + 1];
            }
            float2 v0 = {acc[mi][ni][0] + bb0, acc[mi][ni][1] + bb1};
            float2 v1 = {acc[mi][ni][2] + bb0, acc[mi][ni][3] + bb1};
            if (col0 < rope_n) {
                const int p = (col0 & 127) >> 1;
                float c0 = cosT[s0 * 64 + p], sn0 = sinT[s0 * 64 + p];
                float c1 = cosT[s1 * 64 + p], sn1 = sinT[s1 * 64 + p];
                float2 r0 = {v0.x * c0 - v0.y * sn0, v0.x * sn0 + v0.y * c0};
                float2 r1 = {v1.x * c1 - v1.y * sn1, v1.x * sn1 + v1.y * c1};
                v0 = r0; v1 = r1;
            }
            *(float2*)(dst + (size_t)row0 * stride + ccol) = v0;
            *(float2*)(dst + (size_t)row1 * stride + ccol) = v1;
        }
    }
}

// ===========================================================================
// Tensor-core flash attention (R10 exact: cvt4hl loaders, pair epilogue to g_ap)
// ===========================================================================
#define LQA 136
#define LPV 72
#define ATTN_SMEM ((2 * 128 * LQA + 4 * 64 * LQA + 2 * 128 * LPV) * 2)

__device__ __forceinline__ void cvt4hl(__nv_bfloat16* dhi, __nv_bfloat16* dlo, float4 v)
{
    float f[4] = {v.x, v.y, v.z, v.w};
    __nv_bfloat16 h[4], l[4];
#pragma unroll
    for (int i = 0; i < 4; ++i) {
        h[i] = __float2bfloat16(f[i]);
        l[i] = __float2bfloat16(f[i] - __bfloat162float(h[i]));
    }
    *(uint2*)dhi = *(const uint2*)h;
    *(uint2*)dlo = *(const uint2*)l;
}

__global__ void __launch_bounds__(256) attn_tc_kernel()
{
    extern __shared__ __align__(16) __nv_bfloat16 smb[];
    __nv_bfloat16* Qhi = smb;
    __nv_bfloat16* Qlo = Qhi + 128 * LQA;
    __nv_bfloat16* Khi = Qlo + 128 * LQA;
    __nv_bfloat16* Klo = Khi + 64 * LQA;
    __nv_bfloat16* Vhi = Klo + 64 * LQA;
    __nv_bfloat16* Vlo = Vhi + 64 * LQA;
    __nv_bfloat16* Phi = Vlo + 64 * LQA;
    __nv_bfloat16* Plo = Phi + 128 * LPV;

    const int qt = blockIdx.x, h = blockIdx.y, b = blockIdx.z;
    const int kvh = h / NREP;
    const int tid = threadIdx.x;
    const int lane = tid & 31, w = tid >> 5;
    const int qi0 = qt << 7;

    {
        const float* qg = g_q + (size_t)(b * Sn + qi0) * Dn + h * HDn;
        int r = tid >> 1, c0 = (tid & 1) << 6;
#pragma unroll
        for (int c = 0; c < 64; c += 4) {
            float4 v = *(const float4*)(qg + (size_t)r * Dn + c0 + c);
            cvt4hl(Qhi + r * LQA + c0 + c, Qlo + r * LQA + c0 + c, v);
        }
    }

    const int a_row_l = lane & 15;
    const int a_coff  = (lane >> 4) << 3;
    const int b_row_l = ((lane >> 4) << 3) + (lane & 7);
    const int b_coff  = ((lane >> 3) & 1) << 3;
    const int t_row = (((lane >> 3) & 1) << 3) + (lane & 7);
    const int t_col = (lane >> 4) << 3;

    const uint32_t qhi_b = (uint32_t)__cvta_generic_to_shared(Qhi);
    const uint32_t qlo_b = (uint32_t)__cvta_generic_to_shared(Qlo);
    const uint32_t khi_b = (uint32_t)__cvta_generic_to_shared(Khi);
    const uint32_t klo_b = (uint32_t)__cvta_generic_to_shared(Klo);
    const uint32_t vhi_b = (uint32_t)__cvta_generic_to_shared(Vhi);
    const uint32_t vlo_b = (uint32_t)__cvta_generic_to_shared(Vlo);
    const uint32_t phi_b = (uint32_t)__cvta_generic_to_shared(Phi);
    const uint32_t plo_b = (uint32_t)__cvta_generic_to_shared(Plo);

    const int g  = lane >> 2;
    const int t4 = lane & 3;
    const int qglob0 = qi0 + w * 16 + g;
    const int qglob1 = qglob0 + 8;

    float oacc[16][4];
#pragma unroll
    for (int i = 0; i < 16; ++i)
#pragma unroll
        for (int e = 0; e < 4; ++e) oacc[i][e] = 0.f;
    float m0 = -1e30f, m1 = -1e30f, l0 = 0.f, l1 = 0.f;

    const float* kg_base = g_k + (size_t)(b * Sn) * KVD + kvh * HDn;
    const float* vg_base = g_v + (size_t)(b * Sn) * KVD + kvh * HDn;

    const int jmax = qi0 + 64;
    for (int j0 = 0; j0 <= jmax; j0 += 64) {
        __syncthreads();
        {
            int r = tid >> 2, c0 = (tid & 3) << 5;
            const float* kg = kg_base + (size_t)(j0 + r) * KVD + c0;
            const float* vg = vg_base + (size_t)(j0 + r) * KVD + c0;
#pragma unroll
            for (int c = 0; c < 32; c += 4) {
                cvt4hl(Khi + r * LQA + c0 + c, Klo + r * LQA + c0 + c,
                       *(const float4*)(kg + c));
                cvt4hl(Vhi + r * LQA + c0 + c, Vlo + r * LQA + c0 + c,
                       *(const float4*)(vg + c));
            }
        }
        __syncthreads();

        float sacc[8][4];
#pragma unroll
        for (int i = 0; i < 8; ++i)
#pragma unroll
            for (int e = 0; e < 4; ++e) sacc[i][e] = 0.f;

#pragma unroll
        for (int pass = 0; pass < 3; ++pass) {
            const uint32_t ab = (pass == 2) ? qlo_b : qhi_b;
            const uint32_t bb = (pass == 1) ? klo_b : khi_b;
#pragma unroll
            for (int ks = 0; ks < 8; ++ks) {
                const int kk = ks << 4;
                uint32_t afr[4];
                ldsm4(afr[0], afr[1], afr[2], afr[3],
                      ab + (uint32_t)(((w * 16 + a_row_l) * LQA + kk + a_coff) * 2));
                uint32_t bfr[4][4];
#pragma unroll
                for (int nq = 0; nq < 4; ++nq)
                    ldsm4(bfr[nq][0], bfr[nq][1], bfr[nq][2], bfr[nq][3],
                          bb + (uint32_t)(((nq * 16 + b_row_l) * LQA + kk + b_coff) * 2));
#pragma unroll
                for (int nq = 0; nq < 4; ++nq) {
                    mma16816(sacc[nq * 2 + 0], afr, bfr[nq][0], bfr[nq][1]);
                    mma16816(sacc[nq * 2 + 1], afr, bfr[nq][2], bfr[nq][3]);
                }
            }
        }

#pragma unroll
        for (int nq = 0; nq < 8; ++nq) {
            int cb = j0 + nq * 8 + t4 * 2;
            float s0 = sacc[nq][0] * SCALE;
            float s1 = sacc[nq][1] * SCALE;
            float s2 = sacc[nq][2] * SCALE;
            float s3 = sacc[nq][3] * SCALE;
            if (cb     > qglob0) s0 = -1e30f;
            if (cb + 1 > qglob0) s1 = -1e30f;
            if (cb     > qglob1) s2 = -1e30f;
            if (cb + 1 > qglob1) s3 = -1e30f;
            sacc[nq][0] = s0; sacc[nq][1] = s1;
            sacc[nq][2] = s2; sacc[nq][3] = s3;
        }

        float rm0 = -1e30f, rm1 = -1e30f;
#pragma unroll
        for (int nq = 0; nq < 8; ++nq) {
            rm0 = fmaxf(rm0, fmaxf(sacc[nq][0], sacc[nq][1]));
            rm1 = fmaxf(rm1, fmaxf(sacc[nq][2], sacc[nq][3]));
        }
        rm0 = fmaxf(rm0, __shfl_xor_sync(0xffffffffu, rm0, 1));
        rm0 = fmaxf(rm0, __shfl_xor_sync(0xffffffffu, rm0, 2));
        rm1 = fmaxf(rm1, __shfl_xor_sync(0xffffffffu, rm1, 1));
        rm1 = fmaxf(rm1, __shfl_xor_sync(0xffffffffu, rm1, 2));
        float mn0 = fmaxf(m0, rm0), mn1 = fmaxf(m1, rm1);
        float al0 = __expf(m0 - mn0), al1 = __expf(m1 - mn1);

        __syncwarp();
        float rs0 = 0.f, rs1 = 0.f;
        const int prow0 = w * 16 + g;
#pragma unroll
        for (int nq = 0; nq < 8; ++nq) {
            int col = nq * 8 + t4 * 2;
            float p0 = __expf(sacc[nq][0] - mn0);
            float p1 = __expf(sacc[nq][1] - mn0);
            float p2 = __expf(sacc[nq][2] - mn1);
            float p3 = __expf(sacc[nq][3] - mn1);
            rs0 += p0 + p1;  rs1 += p2 + p3;
            __nv_bfloat162 h01, l01, h23, l23;
            h01.x = __float2bfloat16(p0);
            h01.y = __float2bfloat16(p1);
            l01.x = __float2bfloat16(p0 - __bfloat162float(h01.x));
            l01.y = __float2bfloat16(p1 - __bfloat162float(h01.y));
            h23.x = __float2bfloat16(p2);
            h23.y = __float2bfloat16(p3);
            l23.x = __float2bfloat16(p2 - __bfloat162float(h23.x));
            l23.y = __float2bfloat16(p3 - __bfloat162float(h23.y));
            *(__nv_bfloat162*)(Phi + prow0 * LPV + col)       = h01;
            *(__nv_bfloat162*)(Plo + prow0 * LPV + col)       = l01;
            *(__nv_bfloat162*)(Phi + (prow0 + 8) * LPV + col) = h23;
            *(__nv_bfloat162*)(Plo + (prow0 + 8) * LPV + col) = l23;
        }
        rs0 += __shfl_xor_sync(0xffffffffu, rs0, 1);
        rs0 += __shfl_xor_sync(0xffffffffu, rs0, 2);
        rs1 += __shfl_xor_sync(0xffffffffu, rs1, 1);
        rs1 += __shfl_xor_sync(0xffffffffu, rs1, 2);
        l0 = l0 * al0 + rs0;  l1 = l1 * al1 + rs1;
        m0 = mn0;  m1 = mn1;
#pragma unroll
        for (int nn = 0; nn < 16; ++nn) {
            oacc[nn][0] *= al0; oacc[nn][1] *= al0;
            oacc[nn][2] *= al1; oacc[nn][3] *= al1;
        }
        __syncwarp();

#pragma unroll
        for (int pass = 0; pass < 3; ++pass) {
            const uint32_t ab = (pass == 2) ? plo_b : phi_b;
            const uint32_t bb = (pass == 1) ? vlo_b : vhi_b;
#pragma unroll
            for (int ks = 0; ks < 4; ++ks) {
                const int kk = ks << 4;
                uint32_t afr[4];
                ldsm4(afr[0], afr[1], afr[2], afr[3],
                      ab + (uint32_t)(((w * 16 + a_row_l) * LPV + kk + a_coff) * 2));
#pragma unroll
                for (int nh = 0; nh < 8; ++nh) {
                    uint32_t b0, b1, b2, b3;
                    ldsm4t(b0, b1, b2, b3,
                           bb + (uint32_t)(((kk + t_row) * LQA + nh * 16 + t_col) * 2));
                    mma16816(oacc[nh * 2 + 0], afr, b0, b1);
                    mma16816(oacc[nh * 2 + 1], afr, b2, b3);
                }
            }
        }
    }

    // epilogue: normalize, write (hi,lo) pairs into g_ap (R10 exact)
    float inv0 = 1.f / l0, inv1 = 1.f / l1;
    __nv_bfloat162* ob0 = g_ap + (size_t)(b * Sn + qglob0) * Dn + h * HDn;
    __nv_bfloat162* ob1 = g_ap + (size_t)(b * Sn + qglob1) * Dn + h * HDn;
#pragma unroll
    for (int nn = 0; nn < 16; ++nn) {
        int col = nn * 8 + t4 * 2;
        __nv_bfloat162 p00 = hl_pair(oacc[nn][0] * inv0);
        __nv_bfloat162 p01 = hl_pair(oacc[nn][1] * inv0);
        __nv_bfloat162 p10 = hl_pair(oacc[nn][2] * inv1);
        __nv_bfloat162 p11 = hl_pair(oacc[nn][3] * inv1);
        uint2 s0, s1;
        s0.x = *(uint32_t*)&p00;  s0.y = *(uint32_t*)&p01;
        s1.x = *(uint32_t*)&p10;  s1.y = *(uint32_t*)&p11;
        *(uint2*)(ob0 + col) = s0;
        *(uint2*)(ob1 + col) = s1;
    }
}

// ===========================================================================
// Launch
// ===========================================================================
extern "C" void kernel_launch(void* const* d_in, const int* in_sizes, int n_in,
                              void* d_out, int out_size)
{
    const float* x    = (const float*)d_in[0];
    const float* wq_w = (const float*)d_in[1];
    const float* wq_b = (const float*)d_in[2];
    const float* wk_w = (const float*)d_in[3];
    const float* wk_b = (const float*)d_in[4];
    const float* wv_w = (const float*)d_in[5];
    const float* wv_b = (const float*)d_in[6];
    const float* wo_w = (const float*)d_in[7];
    const float* fcos = (const float*)d_in[10];
    const float* fsin = (const float*)d_in[11];
    float* out = (float*)d_out;

    float *q_p, *k_p, *v_p;
    __nv_bfloat162 *ap, *wqkvp, *wop;
    cudaGetSymbolAddress((void**)&q_p, g_q);
    cudaGetSymbolAddress((void**)&k_p, g_k);
    cudaGetSymbolAddress((void**)&v_p, g_v);
    cudaGetSymbolAddress((void**)&ap,    g_ap);
    cudaGetSymbolAddress((void**)&wqkvp, g_wqkvp);
    cudaGetSymbolAddress((void**)&wop,   g_wop);

    // Fused pack: all 5 tensors in one launch
    pack_all_kernel<<<PACK_BLOCKS, 256>>>(x, wq_w, wk_w, wv_w, wo_w);

    cudaFuncSetAttribute(gemm_pairs_kernel,
                         cudaFuncAttributeMaxDynamicSharedMemorySize, GEMM_SMEM);

    // Merged QKV projection + fused RoPE
    gemm_pairs_kernel<<<dim3(NQKV / 128, Mn / 128), 256, GEMM_SMEM>>>(
        ap, wqkvp, wq_b, wk_b, wv_b, q_p, k_p, v_p, Dn, Dn + KVD, fcos, fsin);

    // Flash attention (writes hi/lo pairs straight into g_ap)
    cudaFuncSetAttribute(attn_tc_kernel, cudaFuncAttributeMaxDynamicSharedMemorySize,
                         ATTN_SMEM);
    attn_tc_kernel<<<dim3(Sn / 128, Hn, Bn), 256, ATTN_SMEM>>>();

    // O projection straight into d_out (no rope, no bias)
    gemm_pairs_kernel<<<dim3(Dn / 128, Mn / 128), 256, GEMM_SMEM>>>(
        ap, wop, nullptr, nullptr, nullptr, out, out, out, Dn, 0, fcos, fsin);
}

// round 17
// speedup vs baseline: 1.0976x; 1.0238x over previous
// R16: R10 exact (best, 3455.6us) + longest-first attention block ordering
// (qt = gridDim.x-1-blockIdx.x; causal blocks have 16x duration spread and
// were launched shortest-first). All arithmetic bit-identical to R10.
// Label: "r10-attn-longest-first".
#include <cuda_runtime.h>
#include <cuda_bf16.h>
#include <cstdint>

// Problem constants (Qwen2 GQA): B=2, S=2048, D=3584, H=28, KV=4, HD=128
#define Bn    2
#define Sn    2048
#define Dn    3584
#define Hn    28
#define KVn   4
#define HDn   128
#define NREP  7
#define Mn    (Bn * Sn)          // 4096
#define KVD   (KVn * HDn)        // 512
#define NQKV  (Dn + 2 * KVD)     // 4608
#define SCALE 0.08838834764831845f

// fp32 intermediates
__device__ float g_q[(size_t)Mn * Dn];
__device__ float g_k[(size_t)Mn * KVD];
__device__ float g_v[(size_t)Mn * KVD];
// planar (hi,lo) bf16 pair arrays
__device__ __nv_bfloat162 g_ap   [(size_t)Mn   * Dn];   // x pairs, later attn pairs
__device__ __nv_bfloat162 g_wqkvp[(size_t)NQKV * Dn];   // wq|wk|wv stacked rows
__device__ __nv_bfloat162 g_wop  [(size_t)Dn   * Dn];

// ===========================================================================
// mma/ldsm helpers
// ===========================================================================
__device__ __forceinline__ void ldsm4(uint32_t& r0, uint32_t& r1,
                                      uint32_t& r2, uint32_t& r3, uint32_t addr)
{
    asm volatile("ldmatrix.sync.aligned.m8n8.x4.shared.b16 {%0,%1,%2,%3}, [%4];\n"
                 : "=r"(r0), "=r"(r1), "=r"(r2), "=r"(r3) : "r"(addr));
}

__device__ __forceinline__ void ldsm4t(uint32_t& r0, uint32_t& r1,
                                       uint32_t& r2, uint32_t& r3, uint32_t addr)
{
    asm volatile("ldmatrix.sync.aligned.m8n8.x4.trans.shared.b16 {%0,%1,%2,%3}, [%4];\n"
                 : "=r"(r0), "=r"(r1), "=r"(r2), "=r"(r3) : "r"(addr));
}

__device__ __forceinline__ void mma16816(float* c, const uint32_t* a,
                                         uint32_t b0, uint32_t b1)
{
    asm volatile(
        "mma.sync.aligned.m16n8k16.row.col.f32.bf16.bf16.f32 "
        "{%0,%1,%2,%3}, {%4,%5,%6,%7}, {%8,%9}, {%0,%1,%2,%3};\n"
        : "+f"(c[0]), "+f"(c[1]), "+f"(c[2]), "+f"(c[3])
        : "r"(a[0]), "r"(a[1]), "r"(a[2]), "r"(a[3]), "r"(b0), "r"(b1));
}

__device__ __forceinline__ __nv_bfloat162 hl_pair(float v)
{
    __nv_bfloat162 p;
    p.x = __float2bfloat16(v);
    p.y = __float2bfloat16(v - __bfloat162float(p.x));
    return p;
}

// ===========================================================================
// Fused pack (R9, verified): fp32 -> interleaved (hi,lo) pair arrays
// ===========================================================================
#define PR0 ((size_t)Mn * Dn)
#define PR1 (PR0 + (size_t)Dn * Dn)
#define PR2 (PR1 + (size_t)KVD * Dn)
#define PR3 (PR2 + (size_t)KVD * Dn)
#define PR4 (PR3 + (size_t)Dn * Dn)
#define PACK_BLOCKS ((int)(PR4 / 16 / 256))

__global__ void pack_all_kernel(
    const float* __restrict__ x,  const float* __restrict__ wq,
    const float* __restrict__ wk, const float* __restrict__ wv,
    const float* __restrict__ wo)
{
    size_t base = ((size_t)blockIdx.x * blockDim.x + threadIdx.x) << 4;
    if (base >= PR4) return;

    const float* in;  __nv_bfloat162* out;  size_t off;
    if (base < PR0)      { in = x;  out = g_ap;                               off = base; }
    else if (base < PR1) { in = wq; out = g_wqkvp;                            off = base - PR0; }
    else if (base < PR2) { in = wk; out = g_wqkvp + (size_t)Dn * Dn;          off = base - PR1; }
    else if (base < PR3) { in = wv; out = g_wqkvp + (size_t)(Dn + KVD) * Dn;  off = base - PR2; }
    else                 { in = wo; out = g_wop;                              off = base - PR3; }

    float4 f[4];
#pragma unroll
    for (int j = 0; j < 4; ++j)
        f[j] = *(const float4*)(in + off + j * 4);

#pragma unroll
    for (int j = 0; j < 4; ++j) {
        float ff[4] = {f[j].x, f[j].y, f[j].z, f[j].w};
        __nv_bfloat162 o[4];
#pragma unroll
        for (int i = 0; i < 4; ++i)
            o[i] = hl_pair(ff[i]);
        *(uint4*)(out + off + j * 4) = *(const uint4*)o;
    }
}

// ===========================================================================
// Planar bf16-split3 GEMM (R10 exact: 256 thr, 8 warps 4Mx2N, 32x64 warp
// tile, 2 CTAs/SM, LDP=24 planes, double buffer, one barrier per K16).
// ===========================================================================
#define LDP 24
#define PLANE (128 * LDP)              // 3072 bf16 = 6144 B
#define STAGE_E (4 * PLANE)
#define GEMM_SMEM (2 * STAGE_E * 2)    // 49152 bytes

__device__ __forceinline__ void split_store(__nv_bfloat16* hip, __nv_bfloat16* lop,
                                            uint4 p0, uint4 p1)
{
    uint2 h0, l0, h1, l1;
    h0.x = (p0.x & 0xFFFFu) | (p0.y << 16);
    h0.y = (p0.z & 0xFFFFu) | (p0.w << 16);
    l0.x = (p0.x >> 16)     | (p0.y & 0xFFFF0000u);
    l0.y = (p0.z >> 16)     | (p0.w & 0xFFFF0000u);
    h1.x = (p1.x & 0xFFFFu) | (p1.y << 16);
    h1.y = (p1.z & 0xFFFFu) | (p1.w << 16);
    l1.x = (p1.x >> 16)     | (p1.y & 0xFFFF0000u);
    l1.y = (p1.z >> 16)     | (p1.w & 0xFFFF0000u);
    *(uint2*)hip       = h0;  *(uint2*)(hip + 4) = h1;
    *(uint2*)lop       = l0;  *(uint2*)(lop + 4) = l1;
}

__global__ void __launch_bounds__(256, 2) gemm_pairs_kernel(
    const __nv_bfloat162* __restrict__ A, const __nv_bfloat162* __restrict__ W,
    const float* __restrict__ bq, const float* __restrict__ bk,
    const float* __restrict__ bv,
    float* __restrict__ qd, float* __restrict__ kd, float* __restrict__ vd,
    int K, int rope_n,
    const float* __restrict__ cosT, const float* __restrict__ sinT)
{
    extern __shared__ __align__(16) __nv_bfloat16 smg[];

    const int tid  = threadIdx.x;
    const int lane = tid & 31, wid = tid >> 5;
    const int m0 = blockIdx.y << 7, n0 = blockIdx.x << 7;
    const int wm = (wid & 3) << 5;
    const int wn = (wid >> 2) << 6;

    const int pr = tid >> 1;
    const int pc = (tid & 1) << 3;
    const __nv_bfloat162* Ag = A + (size_t)(m0 + pr) * K + pc;
    const __nv_bfloat162* Wg = W + (size_t)(n0 + pr) * K + pc;
    const int soff = pr * LDP + pc;

    const int a_row  = wm + (lane & 15);
    const int a_coff = (lane >> 4) << 3;
    const int b_row  = wn + ((lane >> 4) << 3) + (lane & 7);
    const int b_coff = ((lane >> 3) & 1) << 3;
    const uint32_t s_base = (uint32_t)__cvta_generic_to_shared(smg);

    float acc[2][8][4];
#pragma unroll
    for (int i = 0; i < 2; ++i)
#pragma unroll
        for (int j = 0; j < 8; ++j)
#pragma unroll
            for (int e = 0; e < 4; ++e) acc[i][j][e] = 0.f;

    uint4 ra0 = *(const uint4*)(Ag),     ra1 = *(const uint4*)(Ag + 4);
    uint4 rw0 = *(const uint4*)(Wg),     rw1 = *(const uint4*)(Wg + 4);
    split_store(smg + soff,             smg + PLANE + soff,     ra0, ra1);
    split_store(smg + 2 * PLANE + soff, smg + 3 * PLANE + soff, rw0, rw1);
    if (16 < K) {
        ra0 = *(const uint4*)(Ag + 16);  ra1 = *(const uint4*)(Ag + 20);
        rw0 = *(const uint4*)(Wg + 16);  rw1 = *(const uint4*)(Wg + 20);
    }

    int cur = 0;
    for (int k0 = 0; k0 < K; k0 += 16) {
        __syncthreads();

        if (k0 + 16 < K) {
            __nv_bfloat16* nst = smg + (cur ^ 1) * STAGE_E;
            split_store(nst + soff,             nst + PLANE + soff,     ra0, ra1);
            split_store(nst + 2 * PLANE + soff, nst + 3 * PLANE + soff, rw0, rw1);
            if (k0 + 32 < K) {
                ra0 = *(const uint4*)(Ag + k0 + 32);
                ra1 = *(const uint4*)(Ag + k0 + 36);
                rw0 = *(const uint4*)(Wg + k0 + 32);
                rw1 = *(const uint4*)(Wg + k0 + 36);
            }
        }

        const uint32_t st  = s_base + (uint32_t)(cur * STAGE_E * 2);
        const uint32_t ahi = st;
        const uint32_t alo = st + PLANE * 2;
        const uint32_t whi = st + 2 * PLANE * 2;
        const uint32_t wlo = st + 3 * PLANE * 2;

        uint32_t Ah[2][4], Al[2][4];
#pragma unroll
        for (int mi = 0; mi < 2; ++mi) {
            const uint32_t roff = (uint32_t)(((a_row + mi * 16) * LDP + a_coff) * 2);
            ldsm4(Ah[mi][0], Ah[mi][1], Ah[mi][2], Ah[mi][3], ahi + roff);
            ldsm4(Al[mi][0], Al[mi][1], Al[mi][2], Al[mi][3], alo + roff);
        }

#pragma unroll
        for (int nq = 0; nq < 4; ++nq) {
            const uint32_t broff = (uint32_t)(((nq * 16 + b_row) * LDP + b_coff) * 2);
            uint32_t Bh[4];
            ldsm4(Bh[0], Bh[1], Bh[2], Bh[3], whi + broff);
#pragma unroll
            for (int mi = 0; mi < 2; ++mi) {
                mma16816(acc[mi][nq * 2 + 0], Ah[mi], Bh[0], Bh[1]);   // hi*hi
                mma16816(acc[mi][nq * 2 + 1], Ah[mi], Bh[2], Bh[3]);
            }
#pragma unroll
            for (int mi = 0; mi < 2; ++mi) {
                mma16816(acc[mi][nq * 2 + 0], Al[mi], Bh[0], Bh[1]);   // lo*hi
                mma16816(acc[mi][nq * 2 + 1], Al[mi], Bh[2], Bh[3]);
            }
            uint32_t Bl[4];
            ldsm4(Bl[0], Bl[1], Bl[2], Bl[3], wlo + broff);
#pragma unroll
            for (int mi = 0; mi < 2; ++mi) {
                mma16816(acc[mi][nq * 2 + 0], Ah[mi], Bl[0], Bl[1]);   // hi*lo
                mma16816(acc[mi][nq * 2 + 1], Ah[mi], Bl[2], Bl[3]);
            }
        }
        cur ^= 1;
    }

    // ---- epilogue: region dispatch + bias + optional RoPE ----
    const int g = lane >> 2, t = lane & 3;
#pragma unroll
    for (int mi = 0; mi < 2; ++mi) {
        const int row0 = m0 + wm + mi * 16 + g;
        const int row1 = row0 + 8;
        const int s0 = row0 & (Sn - 1);
        const int s1 = row1 & (Sn - 1);
#pragma unroll
        for (int ni = 0; ni < 8; ++ni) {
            const int col0 = n0 + wn + ni * 8 + t * 2;
            float* dst; int ccol, stride;
            float bb0 = 0.f, bb1 = 0.f;
            if (col0 < Dn) {
                dst = qd; ccol = col0; stride = Dn;
                if (bq) { bb0 = bq[col0]; bb1 = bq[col0 + 1]; }
            } else if (col0 < Dn + KVD) {
                dst = kd; ccol = col0 - Dn; stride = KVD;
                bb0 = bk[ccol]; bb1 = bk[ccol + 1];
            } else {
                dst = vd; ccol = col0 - Dn - KVD; stride = KVD;
                bb0 = bv[ccol]; bb1 = bv[ccol + 1];
            }
            float2 v0 = {acc[mi][ni][0] + bb0, acc[mi][ni][1] + bb1};
            float2 v1 = {acc[mi][ni][2] + bb0, acc[mi][ni][3] + bb1};
            if (col0 < rope_n) {
                const int p = (col0 & 127) >> 1;
                float c0 = cosT[s0 * 64 + p], sn0 = sinT[s0 * 64 + p];
                float c1 = cosT[s1 * 64 + p], sn1 = sinT[s1 * 64 + p];
                float2 r0 = {v0.x * c0 - v0.y * sn0, v0.x * sn0 + v0.y * c0};
                float2 r1 = {v1.x * c1 - v1.y * sn1, v1.x * sn1 + v1.y * c1};
                v0 = r0; v1 = r1;
            }
            *(float2*)(dst + (size_t)row0 * stride + ccol) = v0;
            *(float2*)(dst + (size_t)row1 * stride + ccol) = v1;
        }
    }
}

// ===========================================================================
// Tensor-core flash attention (R10; ONLY change: longest-first block order)
// ===========================================================================
#define LQA 136
#define LPV 72
#define ATTN_SMEM ((2 * 128 * LQA + 4 * 64 * LQA + 2 * 128 * LPV) * 2)

__device__ __forceinline__ void cvt4hl(__nv_bfloat16* dhi, __nv_bfloat16* dlo, float4 v)
{
    float f[4] = {v.x, v.y, v.z, v.w};
    __nv_bfloat16 h[4], l[4];
#pragma unroll
    for (int i = 0; i < 4; ++i) {
        h[i] = __float2bfloat16(f[i]);
        l[i] = __float2bfloat16(f[i] - __bfloat162float(h[i]));
    }
    *(uint2*)dhi = *(const uint2*)h;
    *(uint2*)dlo = *(const uint2*)l;
}

__global__ void __launch_bounds__(256) attn_tc_kernel()
{
    extern __shared__ __align__(16) __nv_bfloat16 smb[];
    __nv_bfloat16* Qhi = smb;
    __nv_bfloat16* Qlo = Qhi + 128 * LQA;
    __nv_bfloat16* Khi = Qlo + 128 * LQA;
    __nv_bfloat16* Klo = Khi + 64 * LQA;
    __nv_bfloat16* Vhi = Klo + 64 * LQA;
    __nv_bfloat16* Vlo = Vhi + 64 * LQA;
    __nv_bfloat16* Phi = Vlo + 64 * LQA;
    __nv_bfloat16* Plo = Phi + 128 * LPV;

    // longest-first: big q-tiles (most j-iterations) get the lowest bids
    const int qt = (int)gridDim.x - 1 - (int)blockIdx.x;
    const int h = blockIdx.y, b = blockIdx.z;
    const int kvh = h / NREP;
    const int tid = threadIdx.x;
    const int lane = tid & 31, w = tid >> 5;
    const int qi0 = qt << 7;

    {
        const float* qg = g_q + (size_t)(b * Sn + qi0) * Dn + h * HDn;
        int r = tid >> 1, c0 = (tid & 1) << 6;
#pragma unroll
        for (int c = 0; c < 64; c += 4) {
            float4 v = *(const float4*)(qg + (size_t)r * Dn + c0 + c);
            cvt4hl(Qhi + r * LQA + c0 + c, Qlo + r * LQA + c0 + c, v);
        }
    }

    const int a_row_l = lane & 15;
    const int a_coff  = (lane >> 4) << 3;
    const int b_row_l = ((lane >> 4) << 3) + (lane & 7);
    const int b_coff  = ((lane >> 3) & 1) << 3;
    const int t_row = (((lane >> 3) & 1) << 3) + (lane & 7);
    const int t_col = (lane >> 4) << 3;

    const uint32_t qhi_b = (uint32_t)__cvta_generic_to_shared(Qhi);
    const uint32_t qlo_b = (uint32_t)__cvta_generic_to_shared(Qlo);
    const uint32_t khi_b = (uint32_t)__cvta_generic_to_shared(Khi);
    const uint32_t klo_b = (uint32_t)__cvta_generic_to_shared(Klo);
    const uint32_t vhi_b = (uint32_t)__cvta_generic_to_shared(Vhi);
    const uint32_t vlo_b = (uint32_t)__cvta_generic_to_shared(Vlo);
    const uint32_t phi_b = (uint32_t)__cvta_generic_to_shared(Phi);
    const uint32_t plo_b = (uint32_t)__cvta_generic_to_shared(Plo);

    const int g  = lane >> 2;
    const int t4 = lane & 3;
    const int qglob0 = qi0 + w * 16 + g;
    const int qglob1 = qglob0 + 8;

    float oacc[16][4];
#pragma unroll
    for (int i = 0; i < 16; ++i)
#pragma unroll
        for (int e = 0; e < 4; ++e) oacc[i][e] = 0.f;
    float m0 = -1e30f, m1 = -1e30f, l0 = 0.f, l1 = 0.f;

    const float* kg_base = g_k + (size_t)(b * Sn) * KVD + kvh * HDn;
    const float* vg_base = g_v + (size_t)(b * Sn) * KVD + kvh * HDn;

    const int jmax = qi0 + 64;
    for (int j0 = 0; j0 <= jmax; j0 += 64) {
        __syncthreads();
        {
            int r = tid >> 2, c0 = (tid & 3) << 5;
            const float* kg = kg_base + (size_t)(j0 + r) * KVD + c0;
            const float* vg = vg_base + (size_t)(j0 + r) * KVD + c0;
#pragma unroll
            for (int c = 0; c < 32; c += 4) {
                cvt4hl(Khi + r * LQA + c0 + c, Klo + r * LQA + c0 + c,
                       *(const float4*)(kg + c));
                cvt4hl(Vhi + r * LQA + c0 + c, Vlo + r * LQA + c0 + c,
                       *(const float4*)(vg + c));
            }
        }
        __syncthreads();

        float sacc[8][4];
#pragma unroll
        for (int i = 0; i < 8; ++i)
#pragma unroll
            for (int e = 0; e < 4; ++e) sacc[i][e] = 0.f;

#pragma unroll
        for (int pass = 0; pass < 3; ++pass) {
            const uint32_t ab = (pass == 2) ? qlo_b : qhi_b;
            const uint32_t bb = (pass == 1) ? klo_b : khi_b;
#pragma unroll
            for (int ks = 0; ks < 8; ++ks) {
                const int kk = ks << 4;
                uint32_t afr[4];
                ldsm4(afr[0], afr[1], afr[2], afr[3],
                      ab + (uint32_t)(((w * 16 + a_row_l) * LQA + kk + a_coff) * 2));
                uint32_t bfr[4][4];
#pragma unroll
                for (int nq = 0; nq < 4; ++nq)
                    ldsm4(bfr[nq][0], bfr[nq][1], bfr[nq][2], bfr[nq][3],
                          bb + (uint32_t)(((nq * 16 + b_row_l) * LQA + kk + b_coff) * 2));
#pragma unroll
                for (int nq = 0; nq < 4; ++nq) {
                    mma16816(sacc[nq * 2 + 0], afr, bfr[nq][0], bfr[nq][1]);
                    mma16816(sacc[nq * 2 + 1], afr, bfr[nq][2], bfr[nq][3]);
                }
            }
        }

#pragma unroll
        for (int nq = 0; nq < 8; ++nq) {
            int cb = j0 + nq * 8 + t4 * 2;
            float s0 = sacc[nq][0] * SCALE;
            float s1 = sacc[nq][1] * SCALE;
            float s2 = sacc[nq][2] * SCALE;
            float s3 = sacc[nq][3] * SCALE;
            if (cb     > qglob0) s0 = -1e30f;
            if (cb + 1 > qglob0) s1 = -1e30f;
            if (cb     > qglob1) s2 = -1e30f;
            if (cb + 1 > qglob1) s3 = -1e30f;
            sacc[nq][0] = s0; sacc[nq][1] = s1;
            sacc[nq][2] = s2; sacc[nq][3] = s3;
        }

        float rm0 = -1e30f, rm1 = -1e30f;
#pragma unroll
        for (int nq = 0; nq < 8; ++nq) {
            rm0 = fmaxf(rm0, fmaxf(sacc[nq][0], sacc[nq][1]));
            rm1 = fmaxf(rm1, fmaxf(sacc[nq][2], sacc[nq][3]));
        }
        rm0 = fmaxf(rm0, __shfl_xor_sync(0xffffffffu, rm0, 1));
        rm0 = fmaxf(rm0, __shfl_xor_sync(0xffffffffu, rm0, 2));
        rm1 = fmaxf(rm1, __shfl_xor_sync(0xffffffffu, rm1, 1));
        rm1 = fmaxf(rm1, __shfl_xor_sync(0xffffffffu, rm1, 2));
        float mn0 = fmaxf(m0, rm0), mn1 = fmaxf(m1, rm1);
        float al0 = __expf(m0 - mn0), al1 = __expf(m1 - mn1);

        __syncwarp();
        float rs0 = 0.f, rs1 = 0.f;
        const int prow0 = w * 16 + g;
#pragma unroll
        for (int nq = 0; nq < 8; ++nq) {
            int col = nq * 8 + t4 * 2;
            float p0 = __expf(sacc[nq][0] - mn0);
            float p1 = __expf(sacc[nq][1] - mn0);
            float p2 = __expf(sacc[nq][2] - mn1);
            float p3 = __expf(sacc[nq][3] - mn1);
            rs0 += p0 + p1;  rs1 += p2 + p3;
            __nv_bfloat162 h01, l01, h23, l23;
            h01.x = __float2bfloat16(p0);
            h01.y = __float2bfloat16(p1);
            l01.x = __float2bfloat16(p0 - __bfloat162float(h01.x));
            l01.y = __float2bfloat16(p1 - __bfloat162float(h01.y));
            h23.x = __float2bfloat16(p2);
            h23.y = __float2bfloat16(p3);
            l23.x = __float2bfloat16(p2 - __bfloat162float(h23.x));
            l23.y = __float2bfloat16(p3 - __bfloat162float(h23.y));
            *(__nv_bfloat162*)(Phi + prow0 * LPV + col)       = h01;
            *(__nv_bfloat162*)(Plo + prow0 * LPV + col)       = l01;
            *(__nv_bfloat162*)(Phi + (prow0 + 8) * LPV + col) = h23;
            *(__nv_bfloat162*)(Plo + (prow0 + 8) * LPV + col) = l23;
        }
        rs0 += __shfl_xor_sync(0xffffffffu, rs0, 1);
        rs0 += __shfl_xor_sync(0xffffffffu, rs0, 2);
        rs1 += __shfl_xor_sync(0xffffffffu, rs1, 1);
        rs1 += __shfl_xor_sync(0xffffffffu, rs1, 2);
        l0 = l0 * al0 + rs0;  l1 = l1 * al1 + rs1;
        m0 = mn0;  m1 = mn1;
#pragma unroll
        for (int nn = 0; nn < 16; ++nn) {
            oacc[nn][0] *= al0; oacc[nn][1] *= al0;
            oacc[nn][2] *= al1; oacc[nn][3] *= al1;
        }
        __syncwarp();

#pragma unroll
        for (int pass = 0; pass < 3; ++pass) {
            const uint32_t ab = (pass == 2) ? plo_b : phi_b;
            const uint32_t bb = (pass == 1) ? vlo_b : vhi_b;
#pragma unroll
            for (int ks = 0; ks < 4; ++ks) {
                const int kk = ks << 4;
                uint32_t afr[4];
                ldsm4(afr[0], afr[1], afr[2], afr[3],
                      ab + (uint32_t)(((w * 16 + a_row_l) * LPV + kk + a_coff) * 2));
#pragma unroll
                for (int nh = 0; nh < 8; ++nh) {
                    uint32_t b0, b1, b2, b3;
                    ldsm4t(b0, b1, b2, b3,
                           bb + (uint32_t)(((kk + t_row) * LQA + nh * 16 + t_col) * 2));
                    mma16816(oacc[nh * 2 + 0], afr, b0, b1);
                    mma16816(oacc[nh * 2 + 1], afr, b2, b3);
                }
            }
        }
    }

    // epilogue: normalize, write (hi,lo) pairs into g_ap
    float inv0 = 1.f / l0, inv1 = 1.f / l1;
    __nv_bfloat162* ob0 = g_ap + (size_t)(b * Sn + qglob0) * Dn + h * HDn;
    __nv_bfloat162* ob1 = g_ap + (size_t)(b * Sn + qglob1) * Dn + h * HDn;
#pragma unroll
    for (int nn = 0; nn < 16; ++nn) {
        int col = nn * 8 + t4 * 2;
        __nv_bfloat162 p00 = hl_pair(oacc[nn][0] * inv0);
        __nv_bfloat162 p01 = hl_pair(oacc[nn][1] * inv0);
        __nv_bfloat162 p10 = hl_pair(oacc[nn][2] * inv1);
        __nv_bfloat162 p11 = hl_pair(oacc[nn][3] * inv1);
        uint2 s0, s1;
        s0.x = *(uint32_t*)&p00;  s0.y = *(uint32_t*)&p01;
        s1.x = *(uint32_t*)&p10;  s1.y = *(uint32_t*)&p11;
        *(uint2*)(ob0 + col) = s0;
        *(uint2*)(ob1 + col) = s1;
    }
}

// ===========================================================================
// Launch
// ===========================================================================
extern "C" void kernel_launch(void* const* d_in, const int* in_sizes, int n_in,
                              void* d_out, int out_size)
{
    const float* x    = (const float*)d_in[0];
    const float* wq_w = (const float*)d_in[1];
    const float* wq_b = (const float*)d_in[2];
    const float* wk_w = (const float*)d_in[3];
    const float* wk_b = (const float*)d_in[4];
    const float* wv_w = (const float*)d_in[5];
    const float* wv_b = (const float*)d_in[6];
    const float* wo_w = (const float*)d_in[7];
    const float* fcos = (const float*)d_in[10];
    const float* fsin = (const float*)d_in[11];
    float* out = (float*)d_out;

    float *q_p, *k_p, *v_p;
    __nv_bfloat162 *ap, *wqkvp, *wop;
    cudaGetSymbolAddress((void**)&q_p, g_q);
    cudaGetSymbolAddress((void**)&k_p, g_k);
    cudaGetSymbolAddress((void**)&v_p, g_v);
    cudaGetSymbolAddress((void**)&ap,    g_ap);
    cudaGetSymbolAddress((void**)&wqkvp, g_wqkvp);
    cudaGetSymbolAddress((void**)&wop,   g_wop);

    // Fused pack: all 5 tensors in one launch
    pack_all_kernel<<<PACK_BLOCKS, 256>>>(x, wq_w, wk_w, wv_w, wo_w);

    cudaFuncSetAttribute(gemm_pairs_kernel,
                         cudaFuncAttributeMaxDynamicSharedMemorySize, GEMM_SMEM);

    // Merged QKV projection + fused RoPE
    gemm_pairs_kernel<<<dim3(NQKV / 128, Mn / 128), 256, GEMM_SMEM>>>(
        ap, wqkvp, wq_b, wk_b, wv_b, q_p, k_p, v_p, Dn, Dn + KVD, fcos, fsin);

    // Flash attention (longest blocks first; writes hi/lo pairs into g_ap)
    cudaFuncSetAttribute(attn_tc_kernel, cudaFuncAttributeMaxDynamicSharedMemorySize,
                         ATTN_SMEM);
    attn_tc_kernel<<<dim3(Sn / 128, Hn, Bn), 256, ATTN_SMEM>>>();

    // O projection straight into d_out (no rope, no bias)
    gemm_pairs_kernel<<<dim3(Dn / 128, Mn / 128), 256, GEMM_SMEM>>>(
        ap, wop, nullptr, nullptr, nullptr, out, out, out, Dn, 0, fcos, fsin);
}